// round 1
// baseline (speedup 1.0000x reference)
#include <cuda_runtime.h>
#include <math.h>

#define BATCH 4
#define CH    128
#define C8    16
#define NSP   4096
#define CO    160   // 16 q + 16 k + 128 v output rows

// Scratch for projected q/k/v (allocation-free rule -> __device__ globals)
__device__ float g_q[BATCH * C8 * NSP];
__device__ float g_k[BATCH * C8 * NSP];
__device__ float g_v[BATCH * CH * NSP];

extern __shared__ float smem[];

// ---------------------------------------------------------------------------
// Projection kernel: [q;k;v](160, N) = W(160,128) @ x(128, N) + b, per batch.
// Block = (batch, 64-column tile of N). 256 threads, outer-product 4o x 4n.
// ---------------------------------------------------------------------------
#define PT_N      64
#define XS_PITCH  68     // 64 + 4 pad (float4-aligned rows)
#define WT_PITCH  196    // 192 + 4 pad
#define CO_PAD    192

__global__ __launch_bounds__(256) void proj_kernel(
    const float* __restrict__ x,
    const float* __restrict__ Wq, const float* __restrict__ bq,
    const float* __restrict__ Wk, const float* __restrict__ bk,
    const float* __restrict__ Wv, const float* __restrict__ bv)
{
    float* xs = smem;                      // [128][XS_PITCH]
    float* Wt = xs + CH * XS_PITCH;        // [128][WT_PITCH]  (transposed: [c][o])
    float* bs = Wt + CH * WT_PITCH;        // [CO_PAD]

    const int t  = threadIdx.x;
    const int b  = blockIdx.y;
    const int n0 = blockIdx.x * PT_N;

    // Load W transposed into smem: Wt[c][o]
    for (int idx = t; idx < CO * CH; idx += 256) {
        int o = idx / CH, c = idx % CH;
        float w;
        if (o < 16)       w = Wq[o * CH + c];
        else if (o < 32)  w = Wk[(o - 16) * CH + c];
        else              w = Wv[(o - 32) * CH + c];
        Wt[c * WT_PITCH + o] = w;
    }
    // Zero the padded o-rows [160,192)
    for (int idx = t; idx < (CO_PAD - CO) * CH; idx += 256) {
        int o = CO + idx / CH, c = idx % CH;
        Wt[c * WT_PITCH + o] = 0.f;
    }
    for (int o = t; o < CO_PAD; o += 256) {
        float bb = 0.f;
        if (o < 16)       bb = bq[o];
        else if (o < 32)  bb = bk[o - 16];
        else if (o < CO)  bb = bv[o - 32];
        bs[o] = bb;
    }
    // Load x tile (coalesced float4 over n)
    const float* xb = x + (b * CH) * NSP + n0;
    for (int idx4 = t; idx4 < CH * (PT_N / 4); idx4 += 256) {
        int c  = idx4 / (PT_N / 4);
        int nq = idx4 % (PT_N / 4);
        float4 v = *(const float4*)(xb + c * NSP + nq * 4);
        *(float4*)(xs + c * XS_PITCH + nq * 4) = v;
    }
    __syncthreads();

    const int tn = t % 16;   // n group: n = tn*4 .. +3
    const int to = t / 16;   // o group within pass

    for (int pass = 0; pass < 3; ++pass) {
        const int ob = pass * 64 + to * 4;
        float acc[4][4];
        #pragma unroll
        for (int a = 0; a < 4; ++a)
            #pragma unroll
            for (int d = 0; d < 4; ++d) acc[a][d] = 0.f;

        #pragma unroll 4
        for (int c = 0; c < CH; ++c) {
            float4 wv = *(const float4*)(Wt + c * WT_PITCH + ob);
            float4 xv = *(const float4*)(xs + c * XS_PITCH + tn * 4);
            float wa[4] = {wv.x, wv.y, wv.z, wv.w};
            float xa[4] = {xv.x, xv.y, xv.z, xv.w};
            #pragma unroll
            for (int a = 0; a < 4; ++a)
                #pragma unroll
                for (int d = 0; d < 4; ++d)
                    acc[a][d] = fmaf(wa[a], xa[d], acc[a][d]);
        }

        #pragma unroll
        for (int oo = 0; oo < 4; ++oo) {
            int o = ob + oo;
            if (o < CO) {
                float bb = bs[o];
                float4 r;
                r.x = acc[oo][0] + bb;
                r.y = acc[oo][1] + bb;
                r.z = acc[oo][2] + bb;
                r.w = acc[oo][3] + bb;
                float* dst;
                if (o < 16)       dst = g_q + (b * C8 + o) * NSP + n0 + tn * 4;
                else if (o < 32)  dst = g_k + (b * C8 + (o - 16)) * NSP + n0 + tn * 4;
                else              dst = g_v + (b * CH + (o - 32)) * NSP + n0 + tn * 4;
                *(float4*)dst = r;
            }
        }
    }
}

// ---------------------------------------------------------------------------
// Flash-attention kernel. Block = (batch, 64-query tile). 256 threads.
// Online softmax over 64-key tiles; PV acc[4c][8i] in registers.
// ---------------------------------------------------------------------------
#define TI        64
#define TJ        64
#define QK_PITCH  20     // 16 + 4 pad
#define VS_PITCH  132    // 128 + 4 pad
#define PS_PITCH  68     // 64 + 4 pad

__global__ __launch_bounds__(256) void attn_kernel(
    const float* __restrict__ x,
    const float* __restrict__ gamma,
    float* __restrict__ out)
{
    float* qs   = smem;                       // [TI][QK_PITCH]
    float* ks   = qs  + TI * QK_PITCH;        // [TJ][QK_PITCH]
    float* vs   = ks  + TJ * QK_PITCH;        // [TJ][VS_PITCH]  (transposed: [j][c])
    float* ps   = vs  + TJ * VS_PITCH;        // [TJ][PS_PITCH]  (transposed: [j][i])
    float* mrow = ps  + TJ * PS_PITCH;        // [64]
    float* lrow = mrow + 64;                  // [64]
    float* srow = lrow + 64;                  // [64] rescale factors
    float* red  = srow + 64;                  // [4][64] partial row sums

    const int t   = threadIdx.x;
    const int b   = blockIdx.y;
    const int i0g = blockIdx.x * TI;

    // Score-phase mapping
    const int si  = t & 63;     // query i
    const int sjg = t >> 6;     // j group (16 j's each)
    // PV-phase mapping
    const int ii  = t & 7;      // i block
    const int ci  = t >> 3;     // c block
    const int c0  = ci * 4;
    const int pi0 = ii * 8;

    if (t < 64) { mrow[t] = -1e30f; lrow[t] = 0.f; }

    // Load q tile transposed: qs[i][c]
    const float* qb = g_q + (b * C8) * NSP + i0g;
    for (int idx = t; idx < C8 * TI; idx += 256) {
        int c = idx / TI, i = idx % TI;
        qs[i * QK_PITCH + c] = qb[c * NSP + i];
    }

    float acc[4][8];
    #pragma unroll
    for (int a = 0; a < 4; ++a)
        #pragma unroll
        for (int r = 0; r < 8; ++r) acc[a][r] = 0.f;

    __syncthreads();

    // q for this thread's score row, kept in registers for all tiles
    float4 q4[4];
    #pragma unroll
    for (int u = 0; u < 4; ++u)
        q4[u] = *(const float4*)(qs + si * QK_PITCH + u * 4);

    const float* kb = g_k + (b * C8) * NSP;
    const float* vb = g_v + (b * CH) * NSP;

    for (int jt = 0; jt < NSP / TJ; ++jt) {
        const int j0 = jt * TJ;

        // Load k tile transposed: ks[j][c]
        for (int idx = t; idx < C8 * TJ; idx += 256) {
            int c = idx / TJ, j = idx % TJ;
            ks[j * QK_PITCH + c] = kb[c * NSP + j0 + j];
        }
        // Load v tile transposed: vs[j][c] (coalesced float4 reads)
        for (int idx4 = t; idx4 < CH * (TJ / 4); idx4 += 256) {
            int c = idx4 / (TJ / 4);
            int j = (idx4 % (TJ / 4)) * 4;
            float4 vv = *(const float4*)(vb + c * NSP + j0 + j);
            vs[(j + 0) * VS_PITCH + c] = vv.x;
            vs[(j + 1) * VS_PITCH + c] = vv.y;
            vs[(j + 2) * VS_PITCH + c] = vv.z;
            vs[(j + 3) * VS_PITCH + c] = vv.w;
        }
        __syncthreads();

        // Scores: s[i][j] = q_i . k_j  (16-dim dot), stored transposed ps[j][i]
        #pragma unroll 4
        for (int jj = 0; jj < 16; ++jj) {
            int j = sjg * 16 + jj;
            const float* kr = ks + j * QK_PITCH;
            float4 k0 = *(const float4*)(kr + 0);
            float4 k1 = *(const float4*)(kr + 4);
            float4 k2 = *(const float4*)(kr + 8);
            float4 k3 = *(const float4*)(kr + 12);
            float s;
            s = q4[0].x * k0.x;
            s = fmaf(q4[0].y, k0.y, s);
            s = fmaf(q4[0].z, k0.z, s);
            s = fmaf(q4[0].w, k0.w, s);
            s = fmaf(q4[1].x, k1.x, s);
            s = fmaf(q4[1].y, k1.y, s);
            s = fmaf(q4[1].z, k1.z, s);
            s = fmaf(q4[1].w, k1.w, s);
            s = fmaf(q4[2].x, k2.x, s);
            s = fmaf(q4[2].y, k2.y, s);
            s = fmaf(q4[2].z, k2.z, s);
            s = fmaf(q4[2].w, k2.w, s);
            s = fmaf(q4[3].x, k3.x, s);
            s = fmaf(q4[3].y, k3.y, s);
            s = fmaf(q4[3].z, k3.z, s);
            s = fmaf(q4[3].w, k3.w, s);
            ps[j * PS_PITCH + si] = s;
        }
        __syncthreads();

        // Per-row max + rescale factor (64 threads)
        if (t < 64) {
            float mu = -1e30f;
            #pragma unroll 8
            for (int j = 0; j < TJ; ++j)
                mu = fmaxf(mu, ps[j * PS_PITCH + t]);
            float mo = mrow[t];
            float mn = fmaxf(mo, mu);
            srow[t]  = __expf(mo - mn);
            lrow[t] *= srow[t];
            mrow[t]  = mn;
        }
        __syncthreads();

        // exp() in place + partial row sums
        {
            float mi = mrow[si];
            float psum = 0.f;
            #pragma unroll 4
            for (int jj = 0; jj < 16; ++jj) {
                int j = sjg * 16 + jj;
                float p = __expf(ps[j * PS_PITCH + si] - mi);
                ps[j * PS_PITCH + si] = p;
                psum += p;
            }
            red[sjg * 64 + si] = psum;
        }
        // Rescale accumulator by srow (valid until next tile's max phase)
        #pragma unroll
        for (int r = 0; r < 8; ++r) {
            float sc = srow[pi0 + r];
            #pragma unroll
            for (int a = 0; a < 4; ++a) acc[a][r] *= sc;
        }
        __syncthreads();

        if (t < 64)
            lrow[t] += red[t] + red[64 + t] + red[128 + t] + red[192 + t];

        // PV: acc[c][i] += sum_j p[j][i] * v[j][c]
        #pragma unroll 2
        for (int j = 0; j < TJ; ++j) {
            float4 vv = *(const float4*)(vs + j * VS_PITCH + c0);
            float4 p0 = *(const float4*)(ps + j * PS_PITCH + pi0);
            float4 p1 = *(const float4*)(ps + j * PS_PITCH + pi0 + 4);
            float va[4] = {vv.x, vv.y, vv.z, vv.w};
            float pa[8] = {p0.x, p0.y, p0.z, p0.w, p1.x, p1.y, p1.z, p1.w};
            #pragma unroll
            for (int a = 0; a < 4; ++a)
                #pragma unroll
                for (int r = 0; r < 8; ++r)
                    acc[a][r] = fmaf(va[a], pa[r], acc[a][r]);
        }
        __syncthreads();
    }

    // Normalize, stage to smem (reuse vs region), fuse residual, store.
    float* outs = vs;  // 128*64 = 8192 floats <= TJ*VS_PITCH
    #pragma unroll
    for (int r = 0; r < 8; ++r) {
        float inv = 1.f / lrow[pi0 + r];
        #pragma unroll
        for (int a = 0; a < 4; ++a)
            outs[(c0 + a) * TI + (pi0 + r)] = acc[a][r] * inv;
    }
    __syncthreads();

    const float g = gamma[0];
    const float* xb = x + (b * CH) * NSP + i0g;
    float*       ob = out + (b * CH) * NSP + i0g;
    for (int idx4 = t; idx4 < CH * (TI / 4); idx4 += 256) {
        int c = idx4 / (TI / 4);
        int i = (idx4 % (TI / 4)) * 4;
        float4 xv = *(const float4*)(xb + c * NSP + i);
        float4 ov = *(const float4*)(outs + c * TI + i);
        ov.x = fmaf(g, ov.x, xv.x);
        ov.y = fmaf(g, ov.y, xv.y);
        ov.z = fmaf(g, ov.z, xv.z);
        ov.w = fmaf(g, ov.w, xv.w);
        *(float4*)(ob + c * NSP + i) = ov;
    }
}

// ---------------------------------------------------------------------------
extern "C" void kernel_launch(void* const* d_in, const int* in_sizes, int n_in,
                              void* d_out, int out_size)
{
    const float* x     = (const float*)d_in[0];
    const float* Wq    = (const float*)d_in[1];
    const float* bq    = (const float*)d_in[2];
    const float* Wk    = (const float*)d_in[3];
    const float* bk    = (const float*)d_in[4];
    const float* Wv    = (const float*)d_in[5];
    const float* bv    = (const float*)d_in[6];
    const float* gamma = (const float*)d_in[7];
    float* out = (float*)d_out;

    const size_t smem_proj = (CH * XS_PITCH + CH * WT_PITCH + CO_PAD) * sizeof(float);
    const size_t smem_attn = (TI * QK_PITCH + TJ * QK_PITCH + TJ * VS_PITCH +
                              TJ * PS_PITCH + 3 * 64 + 4 * 64) * sizeof(float);

    cudaFuncSetAttribute(proj_kernel, cudaFuncAttributeMaxDynamicSharedMemorySize,
                         (int)smem_proj);
    cudaFuncSetAttribute(attn_kernel, cudaFuncAttributeMaxDynamicSharedMemorySize,
                         (int)smem_attn);

    dim3 gp(NSP / PT_N, BATCH);   // (64, 4)
    proj_kernel<<<gp, 256, smem_proj>>>(x, Wq, bq, Wk, bk, Wv, bv);

    dim3 ga(NSP / TI, BATCH);     // (64, 4)
    attn_kernel<<<ga, 256, smem_attn>>>(x, gamma, out);
}

// round 2
// speedup vs baseline: 1.0019x; 1.0019x over previous
#include <cuda_runtime.h>
#include <math.h>

#define BATCH 4
#define CH    128
#define C8    16
#define NSP   4096
#define CO    160   // 16 q + 16 k + 128 v output rows

// Scratch for projected q/k/v (allocation-free rule -> __device__ globals)
__device__ float g_q[BATCH * C8 * NSP];
__device__ float g_k[BATCH * C8 * NSP];
__device__ float g_v[BATCH * CH * NSP];

extern __shared__ float smem[];

// ---------------------------------------------------------------------------
// Projection kernel: [q;k;v](160, N) = W(160,128) @ x(128, N) + b, per batch.
// Block = (batch, 64-column tile of N). 256 threads, outer-product 4o x 4n.
// ---------------------------------------------------------------------------
#define PT_N      64
#define XS_PITCH  68     // 64 + 4 pad (float4-aligned rows)
#define WT_PITCH  196    // 192 + 4 pad
#define CO_PAD    192

__global__ __launch_bounds__(256) void proj_kernel(
    const float* __restrict__ x,
    const float* __restrict__ Wq, const float* __restrict__ bq,
    const float* __restrict__ Wk, const float* __restrict__ bk,
    const float* __restrict__ Wv, const float* __restrict__ bv)
{
    float* xs = smem;                      // [128][XS_PITCH]
    float* Wt = xs + CH * XS_PITCH;        // [128][WT_PITCH]  (transposed: [c][o])
    float* bs = Wt + CH * WT_PITCH;        // [CO_PAD]

    const int t  = threadIdx.x;
    const int b  = blockIdx.y;
    const int n0 = blockIdx.x * PT_N;

    // Load W transposed into smem: Wt[c][o]
    for (int idx = t; idx < CO * CH; idx += 256) {
        int o = idx / CH, c = idx % CH;
        float w;
        if (o < 16)       w = Wq[o * CH + c];
        else if (o < 32)  w = Wk[(o - 16) * CH + c];
        else              w = Wv[(o - 32) * CH + c];
        Wt[c * WT_PITCH + o] = w;
    }
    // Zero the padded o-rows [160,192)
    for (int idx = t; idx < (CO_PAD - CO) * CH; idx += 256) {
        int o = CO + idx / CH, c = idx % CH;
        Wt[c * WT_PITCH + o] = 0.f;
    }
    for (int o = t; o < CO_PAD; o += 256) {
        float bb = 0.f;
        if (o < 16)       bb = bq[o];
        else if (o < 32)  bb = bk[o - 16];
        else if (o < CO)  bb = bv[o - 32];
        bs[o] = bb;
    }
    // Load x tile (coalesced float4 over n)
    const float* xb = x + (b * CH) * NSP + n0;
    for (int idx4 = t; idx4 < CH * (PT_N / 4); idx4 += 256) {
        int c  = idx4 / (PT_N / 4);
        int nq = idx4 % (PT_N / 4);
        float4 v = *(const float4*)(xb + c * NSP + nq * 4);
        *(float4*)(xs + c * XS_PITCH + nq * 4) = v;
    }
    __syncthreads();

    const int tn = t % 16;   // n group: n = tn*4 .. +3
    const int to = t / 16;   // o group within pass

    for (int pass = 0; pass < 3; ++pass) {
        const int ob = pass * 64 + to * 4;
        float acc[4][4];
        #pragma unroll
        for (int a = 0; a < 4; ++a)
            #pragma unroll
            for (int d = 0; d < 4; ++d) acc[a][d] = 0.f;

        #pragma unroll 4
        for (int c = 0; c < CH; ++c) {
            float4 wv = *(const float4*)(Wt + c * WT_PITCH + ob);
            float4 xv = *(const float4*)(xs + c * XS_PITCH + tn * 4);
            float wa[4] = {wv.x, wv.y, wv.z, wv.w};
            float xa[4] = {xv.x, xv.y, xv.z, xv.w};
            #pragma unroll
            for (int a = 0; a < 4; ++a)
                #pragma unroll
                for (int d = 0; d < 4; ++d)
                    acc[a][d] = fmaf(wa[a], xa[d], acc[a][d]);
        }

        #pragma unroll
        for (int oo = 0; oo < 4; ++oo) {
            int o = ob + oo;
            if (o < CO) {
                float bb = bs[o];
                float4 r;
                r.x = acc[oo][0] + bb;
                r.y = acc[oo][1] + bb;
                r.z = acc[oo][2] + bb;
                r.w = acc[oo][3] + bb;
                float* dst;
                if (o < 16)       dst = g_q + (b * C8 + o) * NSP + n0 + tn * 4;
                else if (o < 32)  dst = g_k + (b * C8 + (o - 16)) * NSP + n0 + tn * 4;
                else              dst = g_v + (b * CH + (o - 32)) * NSP + n0 + tn * 4;
                *(float4*)dst = r;
            }
        }
    }
}

// ---------------------------------------------------------------------------
// Flash-attention kernel. Block = (batch, 64-query tile). 256 threads.
// Online softmax over 64-key tiles; PV acc[4c][8i] in registers.
// ---------------------------------------------------------------------------
#define TI        64
#define TJ        64
#define QK_PITCH  20     // 16 + 4 pad
#define VS_PITCH  132    // 128 + 4 pad
#define PS_PITCH  68     // 64 + 4 pad

__global__ __launch_bounds__(256) void attn_kernel(
    const float* __restrict__ x,
    const float* __restrict__ gamma,
    float* __restrict__ out)
{
    float* qs   = smem;                       // [TI][QK_PITCH]
    float* ks   = qs  + TI * QK_PITCH;        // [TJ][QK_PITCH]
    float* vs   = ks  + TJ * QK_PITCH;        // [TJ][VS_PITCH]  (transposed: [j][c])
    float* ps   = vs  + TJ * VS_PITCH;        // [TJ][PS_PITCH]  (transposed: [j][i])
    float* mrow = ps  + TJ * PS_PITCH;        // [64]
    float* lrow = mrow + 64;                  // [64]
    float* srow = lrow + 64;                  // [64] rescale factors
    float* red  = srow + 64;                  // [4][64] partial row sums

    const int t   = threadIdx.x;
    const int b   = blockIdx.y;
    const int i0g = blockIdx.x * TI;

    // Score-phase mapping
    const int si  = t & 63;     // query i
    const int sjg = t >> 6;     // j group (16 j's each)
    // PV-phase mapping
    const int ii  = t & 7;      // i block
    const int ci  = t >> 3;     // c block
    const int c0  = ci * 4;
    const int pi0 = ii * 8;

    if (t < 64) { mrow[t] = -1e30f; lrow[t] = 0.f; }

    // Load q tile transposed: qs[i][c]
    const float* qb = g_q + (b * C8) * NSP + i0g;
    for (int idx = t; idx < C8 * TI; idx += 256) {
        int c = idx / TI, i = idx % TI;
        qs[i * QK_PITCH + c] = qb[c * NSP + i];
    }

    float acc[4][8];
    #pragma unroll
    for (int a = 0; a < 4; ++a)
        #pragma unroll
        for (int r = 0; r < 8; ++r) acc[a][r] = 0.f;

    __syncthreads();

    // q for this thread's score row, kept in registers for all tiles
    float4 q4[4];
    #pragma unroll
    for (int u = 0; u < 4; ++u)
        q4[u] = *(const float4*)(qs + si * QK_PITCH + u * 4);

    const float* kb = g_k + (b * C8) * NSP;
    const float* vb = g_v + (b * CH) * NSP;

    for (int jt = 0; jt < NSP / TJ; ++jt) {
        const int j0 = jt * TJ;

        // Load k tile transposed: ks[j][c]
        for (int idx = t; idx < C8 * TJ; idx += 256) {
            int c = idx / TJ, j = idx % TJ;
            ks[j * QK_PITCH + c] = kb[c * NSP + j0 + j];
        }
        // Load v tile transposed: vs[j][c] (coalesced float4 reads)
        for (int idx4 = t; idx4 < CH * (TJ / 4); idx4 += 256) {
            int c = idx4 / (TJ / 4);
            int j = (idx4 % (TJ / 4)) * 4;
            float4 vv = *(const float4*)(vb + c * NSP + j0 + j);
            vs[(j + 0) * VS_PITCH + c] = vv.x;
            vs[(j + 1) * VS_PITCH + c] = vv.y;
            vs[(j + 2) * VS_PITCH + c] = vv.z;
            vs[(j + 3) * VS_PITCH + c] = vv.w;
        }
        __syncthreads();

        // Scores: s[i][j] = q_i . k_j  (16-dim dot), stored transposed ps[j][i]
        #pragma unroll 4
        for (int jj = 0; jj < 16; ++jj) {
            int j = sjg * 16 + jj;
            const float* kr = ks + j * QK_PITCH;
            float4 k0 = *(const float4*)(kr + 0);
            float4 k1 = *(const float4*)(kr + 4);
            float4 k2 = *(const float4*)(kr + 8);
            float4 k3 = *(const float4*)(kr + 12);
            float s;
            s = q4[0].x * k0.x;
            s = fmaf(q4[0].y, k0.y, s);
            s = fmaf(q4[0].z, k0.z, s);
            s = fmaf(q4[0].w, k0.w, s);
            s = fmaf(q4[1].x, k1.x, s);
            s = fmaf(q4[1].y, k1.y, s);
            s = fmaf(q4[1].z, k1.z, s);
            s = fmaf(q4[1].w, k1.w, s);
            s = fmaf(q4[2].x, k2.x, s);
            s = fmaf(q4[2].y, k2.y, s);
            s = fmaf(q4[2].z, k2.z, s);
            s = fmaf(q4[2].w, k2.w, s);
            s = fmaf(q4[3].x, k3.x, s);
            s = fmaf(q4[3].y, k3.y, s);
            s = fmaf(q4[3].z, k3.z, s);
            s = fmaf(q4[3].w, k3.w, s);
            ps[j * PS_PITCH + si] = s;
        }
        __syncthreads();

        // Per-row max + rescale factor (64 threads)
        if (t < 64) {
            float mu = -1e30f;
            #pragma unroll 8
            for (int j = 0; j < TJ; ++j)
                mu = fmaxf(mu, ps[j * PS_PITCH + t]);
            float mo = mrow[t];
            float mn = fmaxf(mo, mu);
            srow[t]  = __expf(mo - mn);
            lrow[t] *= srow[t];
            mrow[t]  = mn;
        }
        __syncthreads();

        // exp() in place + partial row sums
        {
            float mi = mrow[si];
            float psum = 0.f;
            #pragma unroll 4
            for (int jj = 0; jj < 16; ++jj) {
                int j = sjg * 16 + jj;
                float p = __expf(ps[j * PS_PITCH + si] - mi);
                ps[j * PS_PITCH + si] = p;
                psum += p;
            }
            red[sjg * 64 + si] = psum;
        }
        // Rescale accumulator by srow (valid until next tile's max phase)
        #pragma unroll
        for (int r = 0; r < 8; ++r) {
            float sc = srow[pi0 + r];
            #pragma unroll
            for (int a = 0; a < 4; ++a) acc[a][r] *= sc;
        }
        __syncthreads();

        if (t < 64)
            lrow[t] += red[t] + red[64 + t] + red[128 + t] + red[192 + t];

        // PV: acc[c][i] += sum_j p[j][i] * v[j][c]
        #pragma unroll 2
        for (int j = 0; j < TJ; ++j) {
            float4 vv = *(const float4*)(vs + j * VS_PITCH + c0);
            float4 p0 = *(const float4*)(ps + j * PS_PITCH + pi0);
            float4 p1 = *(const float4*)(ps + j * PS_PITCH + pi0 + 4);
            float va[4] = {vv.x, vv.y, vv.z, vv.w};
            float pa[8] = {p0.x, p0.y, p0.z, p0.w, p1.x, p1.y, p1.z, p1.w};
            #pragma unroll
            for (int a = 0; a < 4; ++a)
                #pragma unroll
                for (int r = 0; r < 8; ++r)
                    acc[a][r] = fmaf(va[a], pa[r], acc[a][r]);
        }
        __syncthreads();
    }

    // Normalize, stage to smem (reuse vs region), fuse residual, store.
    float* outs = vs;  // 128*64 = 8192 floats <= TJ*VS_PITCH
    #pragma unroll
    for (int r = 0; r < 8; ++r) {
        float inv = 1.f / lrow[pi0 + r];
        #pragma unroll
        for (int a = 0; a < 4; ++a)
            outs[(c0 + a) * TI + (pi0 + r)] = acc[a][r] * inv;
    }
    __syncthreads();

    const float g = gamma[0];
    const float* xb = x + (b * CH) * NSP + i0g;
    float*       ob = out + (b * CH) * NSP + i0g;
    for (int idx4 = t; idx4 < CH * (TI / 4); idx4 += 256) {
        int c = idx4 / (TI / 4);
        int i = (idx4 % (TI / 4)) * 4;
        float4 xv = *(const float4*)(xb + c * NSP + i);
        float4 ov = *(const float4*)(outs + c * TI + i);
        ov.x = fmaf(g, ov.x, xv.x);
        ov.y = fmaf(g, ov.y, xv.y);
        ov.z = fmaf(g, ov.z, xv.z);
        ov.w = fmaf(g, ov.w, xv.w);
        *(float4*)(ob + c * NSP + i) = ov;
    }
}

// ---------------------------------------------------------------------------
extern "C" void kernel_launch(void* const* d_in, const int* in_sizes, int n_in,
                              void* d_out, int out_size)
{
    const float* x     = (const float*)d_in[0];
    const float* Wq    = (const float*)d_in[1];
    const float* bq    = (const float*)d_in[2];
    const float* Wk    = (const float*)d_in[3];
    const float* bk    = (const float*)d_in[4];
    const float* Wv    = (const float*)d_in[5];
    const float* bv    = (const float*)d_in[6];
    const float* gamma = (const float*)d_in[7];
    float* out = (float*)d_out;

    const size_t smem_proj = (CH * XS_PITCH + CH * WT_PITCH + CO_PAD) * sizeof(float);
    const size_t smem_attn = (TI * QK_PITCH + TJ * QK_PITCH + TJ * VS_PITCH +
                              TJ * PS_PITCH + 3 * 64 + 4 * 64) * sizeof(float);

    cudaFuncSetAttribute(proj_kernel, cudaFuncAttributeMaxDynamicSharedMemorySize,
                         (int)smem_proj);
    cudaFuncSetAttribute(attn_kernel, cudaFuncAttributeMaxDynamicSharedMemorySize,
                         (int)smem_attn);

    dim3 gp(NSP / PT_N, BATCH);   // (64, 4)
    proj_kernel<<<gp, 256, smem_proj>>>(x, Wq, bq, Wk, bk, Wv, bv);

    dim3 ga(NSP / TI, BATCH);     // (64, 4)
    attn_kernel<<<ga, 256, smem_attn>>>(x, gamma, out);
}

// round 3
// speedup vs baseline: 1.0654x; 1.0633x over previous
#include <cuda_runtime.h>
#include <math.h>

#define BATCH 4
#define CH    128
#define C8    16
#define NSP   4096
#define CO    160   // 16 q + 16 k + 128 v output rows

// Scratch (allocation-free rule -> __device__ globals)
__device__ __align__(16) float g_q[BATCH * C8 * NSP];
__device__ __align__(16) float g_k[BATCH * C8 * NSP];
__device__ __align__(16) float g_v[BATCH * CH * NSP];
// Split-K partials: [half][b][c][n], and [half][b][n] for m/l
__device__ __align__(16) float g_po[2 * BATCH * CH * NSP];
__device__ float g_m[2 * BATCH * NSP];
__device__ float g_l[2 * BATCH * NSP];

extern __shared__ float smem[];

// ---------------------------------------------------------------------------
// Projection kernel: [q;k;v](160, N) = W(160,128) @ x(128, N) + b, per batch.
// ---------------------------------------------------------------------------
#define PT_N      64
#define XS_PITCH  68
#define WT_PITCH  196
#define CO_PAD    192

__global__ __launch_bounds__(256) void proj_kernel(
    const float* __restrict__ x,
    const float* __restrict__ Wq, const float* __restrict__ bq,
    const float* __restrict__ Wk, const float* __restrict__ bk,
    const float* __restrict__ Wv, const float* __restrict__ bv)
{
    float* xs = smem;                      // [128][XS_PITCH]
    float* Wt = xs + CH * XS_PITCH;        // [128][WT_PITCH]
    float* bs = Wt + CH * WT_PITCH;        // [CO_PAD]

    const int t  = threadIdx.x;
    const int b  = blockIdx.y;
    const int n0 = blockIdx.x * PT_N;

    for (int idx = t; idx < CO * CH; idx += 256) {
        int o = idx / CH, c = idx % CH;
        float w;
        if (o < 16)       w = Wq[o * CH + c];
        else if (o < 32)  w = Wk[(o - 16) * CH + c];
        else              w = Wv[(o - 32) * CH + c];
        Wt[c * WT_PITCH + o] = w;
    }
    for (int idx = t; idx < (CO_PAD - CO) * CH; idx += 256) {
        int o = CO + idx / CH, c = idx % CH;
        Wt[c * WT_PITCH + o] = 0.f;
    }
    for (int o = t; o < CO_PAD; o += 256) {
        float bb = 0.f;
        if (o < 16)       bb = bq[o];
        else if (o < 32)  bb = bk[o - 16];
        else if (o < CO)  bb = bv[o - 32];
        bs[o] = bb;
    }
    const float* xb = x + (b * CH) * NSP + n0;
    for (int idx4 = t; idx4 < CH * (PT_N / 4); idx4 += 256) {
        int c  = idx4 / (PT_N / 4);
        int nq = idx4 % (PT_N / 4);
        float4 v = *(const float4*)(xb + c * NSP + nq * 4);
        *(float4*)(xs + c * XS_PITCH + nq * 4) = v;
    }
    __syncthreads();

    const int tn = t % 16;
    const int to = t / 16;

    for (int pass = 0; pass < 3; ++pass) {
        const int ob = pass * 64 + to * 4;
        float acc[4][4];
        #pragma unroll
        for (int a = 0; a < 4; ++a)
            #pragma unroll
            for (int d = 0; d < 4; ++d) acc[a][d] = 0.f;

        #pragma unroll 4
        for (int c = 0; c < CH; ++c) {
            float4 wv = *(const float4*)(Wt + c * WT_PITCH + ob);
            float4 xv = *(const float4*)(xs + c * XS_PITCH + tn * 4);
            float wa[4] = {wv.x, wv.y, wv.z, wv.w};
            float xa[4] = {xv.x, xv.y, xv.z, xv.w};
            #pragma unroll
            for (int a = 0; a < 4; ++a)
                #pragma unroll
                for (int d = 0; d < 4; ++d)
                    acc[a][d] = fmaf(wa[a], xa[d], acc[a][d]);
        }

        #pragma unroll
        for (int oo = 0; oo < 4; ++oo) {
            int o = ob + oo;
            if (o < CO) {
                float bb = bs[o];
                float4 r;
                r.x = acc[oo][0] + bb;
                r.y = acc[oo][1] + bb;
                r.z = acc[oo][2] + bb;
                r.w = acc[oo][3] + bb;
                float* dst;
                if (o < 16)       dst = g_q + (b * C8 + o) * NSP + n0 + tn * 4;
                else if (o < 32)  dst = g_k + (b * C8 + (o - 16)) * NSP + n0 + tn * 4;
                else              dst = g_v + (b * CH + (o - 32)) * NSP + n0 + tn * 4;
                *(float4*)dst = r;
            }
        }
    }
}

// ---------------------------------------------------------------------------
// Split-K flash attention. Block = (i-tile, batch, j-half). 256 threads.
// Each block handles 2048 keys in 32 tiles of 64; writes (acc, m, l) partials.
// ---------------------------------------------------------------------------
#define TI        64
#define TJ        64
#define HALF_J    (NSP / 2)
#define QK_PITCH  20
#define VS_PITCH  132
#define PS_PITCH  68
// XOR swizzle on the c index of the transposed V tile (16B-chunk granularity)
#define VSWZ(j)   ((((j) >> 2) & 7) << 2)

__global__ __launch_bounds__(256, 3) void attn_kernel()
{
    float* qs   = smem;                       // [TI][QK_PITCH]
    float* ks   = qs  + TI * QK_PITCH;        // [TJ][QK_PITCH]
    float* vs   = ks  + TJ * QK_PITCH;        // [TJ][VS_PITCH]  transposed+swizzled
    float* ps   = vs  + TJ * VS_PITCH;        // [TJ][PS_PITCH]  transposed: [j][i]
    float* mrow = ps  + TJ * PS_PITCH;        // [64]
    float* lrow = mrow + 64;                  // [64]
    float* srow = lrow + 64;                  // [64]
    float* redm = srow + 64;                  // [4][64] partial maxes
    float* reds = redm + 256;                 // [4][64] partial sums

    const int t   = threadIdx.x;
    const int b   = blockIdx.y;
    const int h   = blockIdx.z;               // j-half
    const int i0g = blockIdx.x * TI;

    const int si  = t & 63;     // query i (score/exp phases)
    const int sjg = t >> 6;     // j group of 16
    const int ii  = t & 7;      // PV mapping
    const int ci  = t >> 3;
    const int c0  = ci * 4;
    const int pi0 = ii * 8;

    if (t < 64) { mrow[t] = -1e30f; lrow[t] = 0.f; }

    const float* qb = g_q + (b * C8) * NSP + i0g;
    for (int idx = t; idx < C8 * TI; idx += 256) {
        int c = idx / TI, i = idx % TI;
        qs[i * QK_PITCH + c] = qb[c * NSP + i];
    }

    float acc[4][8];
    #pragma unroll
    for (int a = 0; a < 4; ++a)
        #pragma unroll
        for (int r = 0; r < 8; ++r) acc[a][r] = 0.f;

    __syncthreads();

    float4 q4[4];
    #pragma unroll
    for (int u = 0; u < 4; ++u)
        q4[u] = *(const float4*)(qs + si * QK_PITCH + u * 4);

    const float* kb = g_k + (b * C8) * NSP;
    const float* vb = g_v + (b * CH) * NSP;

    for (int jt = 0; jt < HALF_J / TJ; ++jt) {
        const int j0 = h * HALF_J + jt * TJ;
        const float mo = mrow[si];   // stable: last written 2 barriers ago

        // Load k tile transposed: ks[j][c]
        for (int idx = t; idx < C8 * TJ; idx += 256) {
            int c = idx / TJ, j = idx % TJ;
            ks[j * QK_PITCH + c] = kb[c * NSP + j0 + j];
        }
        // Load v tile transposed+swizzled: vs[j][c ^ swz(j)]
        for (int idx4 = t; idx4 < CH * (TJ / 4); idx4 += 256) {
            int c = idx4 >> 4;
            int j = (idx4 & 15) * 4;
            float4 vv = *(const float4*)(vb + c * NSP + j0 + j);
            int cs = c ^ VSWZ(j);   // same swizzle for rows j..j+3
            vs[(j + 0) * VS_PITCH + cs] = vv.x;
            vs[(j + 1) * VS_PITCH + cs] = vv.y;
            vs[(j + 2) * VS_PITCH + cs] = vv.z;
            vs[(j + 3) * VS_PITCH + cs] = vv.w;
        }
        __syncthreads();

        // Phase A: scores s[i][j] = q_i . k_j, store transposed, track local max
        float lmax = -1e30f;
        #pragma unroll 4
        for (int jj = 0; jj < 16; ++jj) {
            int j = sjg * 16 + jj;
            const float* kr = ks + j * QK_PITCH;
            float4 k0 = *(const float4*)(kr + 0);
            float4 k1 = *(const float4*)(kr + 4);
            float4 k2 = *(const float4*)(kr + 8);
            float4 k3 = *(const float4*)(kr + 12);
            float s;
            s = q4[0].x * k0.x;
            s = fmaf(q4[0].y, k0.y, s);
            s = fmaf(q4[0].z, k0.z, s);
            s = fmaf(q4[0].w, k0.w, s);
            s = fmaf(q4[1].x, k1.x, s);
            s = fmaf(q4[1].y, k1.y, s);
            s = fmaf(q4[1].z, k1.z, s);
            s = fmaf(q4[1].w, k1.w, s);
            s = fmaf(q4[2].x, k2.x, s);
            s = fmaf(q4[2].y, k2.y, s);
            s = fmaf(q4[2].z, k2.z, s);
            s = fmaf(q4[2].w, k2.w, s);
            s = fmaf(q4[3].x, k3.x, s);
            s = fmaf(q4[3].y, k3.y, s);
            s = fmaf(q4[3].z, k3.z, s);
            s = fmaf(q4[3].w, k3.w, s);
            ps[j * PS_PITCH + si] = s;
            lmax = fmaxf(lmax, s);
        }
        redm[sjg * 64 + si] = lmax;
        __syncthreads();

        // Phase C: combine max (4 threads per si compute identical values),
        // exponentiate in place, partial row sums.
        {
            float mu = fmaxf(fmaxf(redm[si], redm[64 + si]),
                             fmaxf(redm[128 + si], redm[192 + si]));
            float mn = fmaxf(mo, mu);
            srow[si] = __expf(mo - mn);   // duplicate same-value write
            mrow[si] = mn;                // duplicate same-value write
            float psum = 0.f;
            #pragma unroll 4
            for (int jj = 0; jj < 16; ++jj) {
                int j = sjg * 16 + jj;
                float p = __expf(ps[j * PS_PITCH + si] - mn);
                ps[j * PS_PITCH + si] = p;
                psum += p;
            }
            reds[sjg * 64 + si] = psum;
        }
        __syncthreads();

        // Phase D: rescale acc, PV, update lrow
        #pragma unroll
        for (int r = 0; r < 8; ++r) {
            float sc = srow[pi0 + r];
            #pragma unroll
            for (int a = 0; a < 4; ++a) acc[a][r] *= sc;
        }
        if (t < 64)
            lrow[t] = lrow[t] * srow[t] +
                      (reds[t] + reds[64 + t]) + (reds[128 + t] + reds[192 + t]);

        #pragma unroll 2
        for (int j = 0; j < TJ; ++j) {
            float4 vv = *(const float4*)(vs + j * VS_PITCH + (c0 ^ VSWZ(j)));
            float4 p0 = *(const float4*)(ps + j * PS_PITCH + pi0);
            float4 p1 = *(const float4*)(ps + j * PS_PITCH + pi0 + 4);
            float va[4] = {vv.x, vv.y, vv.z, vv.w};
            float pa[8] = {p0.x, p0.y, p0.z, p0.w, p1.x, p1.y, p1.z, p1.w};
            #pragma unroll
            for (int a = 0; a < 4; ++a)
                #pragma unroll
                for (int r = 0; r < 8; ++r)
                    acc[a][r] = fmaf(va[a], pa[r], acc[a][r]);
        }
        __syncthreads();
    }

    // Epilogue: stage unnormalized acc, write partials
    float* outs = vs;  // 128*64 floats fit in the vs region
    #pragma unroll
    for (int r = 0; r < 8; ++r) {
        #pragma unroll
        for (int a = 0; a < 4; ++a)
            outs[(c0 + a) * TI + (pi0 + r)] = acc[a][r];
    }
    __syncthreads();

    float* pob = g_po + ((h * BATCH + b) * CH) * NSP + i0g;
    for (int idx4 = t; idx4 < CH * (TI / 4); idx4 += 256) {
        int c = idx4 / (TI / 4);
        int i = (idx4 % (TI / 4)) * 4;
        float4 ov = *(const float4*)(outs + c * TI + i);
        *(float4*)(pob + c * NSP + i) = ov;
    }
    if (t < 64) {
        g_m[(h * BATCH + b) * NSP + i0g + t] = mrow[t];
        g_l[(h * BATCH + b) * NSP + i0g + t] = lrow[t];
    }
}

// ---------------------------------------------------------------------------
// Combine the two j-halves, normalize, fuse gamma*out + x.
// ---------------------------------------------------------------------------
__global__ __launch_bounds__(256) void combine_kernel(
    const float* __restrict__ x,
    const float* __restrict__ gamma,
    float* __restrict__ out)
{
    const int t  = threadIdx.x;
    const int b  = blockIdx.y;
    const int i  = blockIdx.x * 64 + (t & 63);
    const int cg = t >> 6;

    const int nidx = b * NSP + i;
    float m0 = g_m[nidx], m1 = g_m[BATCH * NSP + nidx];
    float l0 = g_l[nidx], l1 = g_l[BATCH * NSP + nidx];
    float M  = fmaxf(m0, m1);
    float a0 = __expf(m0 - M);
    float a1 = __expf(m1 - M);
    float inv = 1.f / (l0 * a0 + l1 * a1);
    const float g = gamma[0];

    #pragma unroll 4
    for (int cc = 0; cc < 32; ++cc) {
        int c = cg * 32 + cc;
        int off = (b * CH + c) * NSP + i;
        float o0 = g_po[off];
        float o1 = g_po[BATCH * CH * NSP + off];
        float xo = x[off];
        out[off] = fmaf(g, (o0 * a0 + o1 * a1) * inv, xo);
    }
}

// ---------------------------------------------------------------------------
extern "C" void kernel_launch(void* const* d_in, const int* in_sizes, int n_in,
                              void* d_out, int out_size)
{
    const float* x     = (const float*)d_in[0];
    const float* Wq    = (const float*)d_in[1];
    const float* bq    = (const float*)d_in[2];
    const float* Wk    = (const float*)d_in[3];
    const float* bk    = (const float*)d_in[4];
    const float* Wv    = (const float*)d_in[5];
    const float* bv    = (const float*)d_in[6];
    const float* gamma = (const float*)d_in[7];
    float* out = (float*)d_out;

    const size_t smem_proj = (CH * XS_PITCH + CH * WT_PITCH + CO_PAD) * sizeof(float);
    const size_t smem_attn = (TI * QK_PITCH + TJ * QK_PITCH + TJ * VS_PITCH +
                              TJ * PS_PITCH + 3 * 64 + 2 * 256) * sizeof(float);

    cudaFuncSetAttribute(proj_kernel, cudaFuncAttributeMaxDynamicSharedMemorySize,
                         (int)smem_proj);
    cudaFuncSetAttribute(attn_kernel, cudaFuncAttributeMaxDynamicSharedMemorySize,
                         (int)smem_attn);

    dim3 gp(NSP / PT_N, BATCH);      // (64, 4)
    proj_kernel<<<gp, 256, smem_proj>>>(x, Wq, bq, Wk, bk, Wv, bv);

    dim3 ga(NSP / TI, BATCH, 2);     // (64, 4, 2) = 512 blocks
    attn_kernel<<<ga, 256, smem_attn>>>();

    dim3 gc(NSP / 64, BATCH);        // (64, 4)
    combine_kernel<<<gc, 256>>>(x, gamma, out);
}

// round 6
// speedup vs baseline: 3.8702x; 3.6328x over previous
#include <cuda_runtime.h>
#include <cuda_bf16.h>
#include <cstdint>
#include <math.h>

#define BATCH 4
#define CH    128
#define C8    16
#define NSP   4096
#define CO    160
#define TI    128
#define TJ    64
#define NTJ   (NSP / TJ)

// bf16 hi/lo operands produced by proj kernel
__device__ __align__(16) __nv_bfloat16 g_q2[BATCH * NSP * 32];  // [b][n][ qh(16) | ql(16) ]
__device__ __align__(16) __nv_bfloat16 g_k2[BATCH * NSP * 32];  // [b][n][ kh(16) | kl(16) ]
__device__ __align__(16) __nv_bfloat16 g_vh[BATCH * CH * NSP];  // [b][c][n]
__device__ __align__(16) __nv_bfloat16 g_vl[BATCH * CH * NSP];

extern __shared__ __align__(16) char dsmem[];

// ---------------------------------------------------------------------------
// helpers
// ---------------------------------------------------------------------------
__device__ __forceinline__ uint32_t smem_u32(const void* p) {
    uint32_t a;
    asm("{ .reg .u64 t; cvta.to.shared.u64 t, %1; cvt.u32.u64 %0, t; }"
        : "=r"(a) : "l"(p));
    return a;
}

#define LDSM4(r, addr) \
    asm volatile("ldmatrix.sync.aligned.m8n8.x4.shared.b16 {%0,%1,%2,%3}, [%4];" \
        : "=r"((r)[0]), "=r"((r)[1]), "=r"((r)[2]), "=r"((r)[3]) : "r"(addr))

// D(+=) = A(m16k16 bf16) * B(k16n8 bf16), f32 accum
#define MMA(d, a, b) \
    asm volatile("mma.sync.aligned.m16n8k16.row.col.f32.bf16.bf16.f32 " \
        "{%0,%1,%2,%3}, {%4,%5,%6,%7}, {%8,%9}, {%0,%1,%2,%3};" \
        : "+f"((d)[0]), "+f"((d)[1]), "+f"((d)[2]), "+f"((d)[3]) \
        : "r"((a)[0]), "r"((a)[1]), "r"((a)[2]), "r"((a)[3]), \
          "r"((b)[0]), "r"((b)[1]))

#define CP16(dst, src) \
    asm volatile("cp.async.cg.shared.global [%0], [%1], 16;" :: "r"(dst), "l"(src))
#define CPCOMMIT() asm volatile("cp.async.commit_group;" ::: "memory")
#define CPWAIT0()  asm volatile("cp.async.wait_group 0;" ::: "memory")

// exp on the FMA pipe: 2^(s*log2e), degree-6 poly of 2^f, f in [0,1)
__device__ __forceinline__ float fexp(float s) {
    float t  = s * 1.4426950408889634f;
    float fl = floorf(t);
    float f  = t - fl;
    float p  =              1.3333558146e-3f;
    p = fmaf(p, f, 9.6181291076e-3f);
    p = fmaf(p, f, 5.5504108664e-2f);
    p = fmaf(p, f, 2.4022650696e-1f);
    p = fmaf(p, f, 6.9314718056e-1f);
    p = fmaf(p, f, 1.0f);
    return p * __int_as_float(((int)fl + 127) << 23);
}

__device__ __forceinline__ uint32_t packbf(float lo, float hi) {
    uint32_t r;
    asm("cvt.rn.bf16x2.f32 %0, %1, %2;" : "=r"(r) : "f"(hi), "f"(lo));
    return r;
}

// ---------------------------------------------------------------------------
// Projection: [q;k;v](160,N) = W @ x + b, emitting bf16 hi/lo operands.
// ---------------------------------------------------------------------------
#define XS_PITCH 68
#define WT_PITCH 65

__global__ __launch_bounds__(256) void proj_kernel(
    const float* __restrict__ x,
    const float* __restrict__ Wq, const float* __restrict__ bq,
    const float* __restrict__ Wk, const float* __restrict__ bk,
    const float* __restrict__ Wv, const float* __restrict__ bv)
{
    float* xs = (float*)dsmem;             // [128][68]
    float* Wt = xs + CH * XS_PITCH;        // [128][65]

    const int t  = threadIdx.x;
    const int b  = blockIdx.y;
    const int n0 = blockIdx.x * 64;

    const float* xb = x + (size_t)(b * CH) * NSP + n0;
    for (int idx4 = t; idx4 < CH * 16; idx4 += 256) {
        int c  = idx4 >> 4;
        int nq = idx4 & 15;
        float4 v = *(const float4*)(xb + (size_t)c * NSP + nq * 4);
        *(float4*)(xs + c * XS_PITCH + nq * 4) = v;
    }

    const int tn = t & 15;
    const int to = t >> 4;

    for (int pass = 0; pass < 3; ++pass) {
        __syncthreads();
        for (int idx = t; idx < 64 * CH; idx += 256) {
            int ol = idx >> 7;
            int c  = idx & 127;
            int o  = pass * 64 + ol;
            float w = 0.f;
            if (o < 16)       w = Wq[o * CH + c];
            else if (o < 32)  w = Wk[(o - 16) * CH + c];
            else if (o < CO)  w = Wv[(o - 32) * CH + c];
            Wt[c * WT_PITCH + ol] = w;
        }
        __syncthreads();

        const int olb = to * 4;
        float acc[4][4];
        #pragma unroll
        for (int a = 0; a < 4; ++a)
            #pragma unroll
            for (int d = 0; d < 4; ++d) acc[a][d] = 0.f;

        #pragma unroll 4
        for (int c = 0; c < CH; ++c) {
            const float* wr = Wt + c * WT_PITCH + olb;
            float wa[4] = {wr[0], wr[1], wr[2], wr[3]};
            float4 xv = *(const float4*)(xs + c * XS_PITCH + tn * 4);
            float xa[4] = {xv.x, xv.y, xv.z, xv.w};
            #pragma unroll
            for (int a = 0; a < 4; ++a)
                #pragma unroll
                for (int d = 0; d < 4; ++d)
                    acc[a][d] = fmaf(wa[a], xa[d], acc[a][d]);
        }

        #pragma unroll
        for (int oo = 0; oo < 4; ++oo) {
            int o = pass * 64 + olb + oo;
            if (o >= CO) continue;
            float bb;
            if (o < 16)       bb = bq[o];
            else if (o < 32)  bb = bk[o - 16];
            else              bb = bv[o - 32];
            float vals[4];
            #pragma unroll
            for (int d = 0; d < 4; ++d) vals[d] = acc[oo][d] + bb;

            if (o < 32) {
                __nv_bfloat16* dst = (o < 16) ? g_q2 : g_k2;
                int oc = (o < 16) ? o : (o - 16);
                #pragma unroll
                for (int d = 0; d < 4; ++d) {
                    int n = n0 + tn * 4 + d;
                    float v = vals[d];
                    __nv_bfloat16 h = __float2bfloat16(v);
                    __nv_bfloat16 l = __float2bfloat16(v - __bfloat162float(h));
                    size_t base = ((size_t)b * NSP + n) * 32;
                    dst[base + oc]      = h;
                    dst[base + oc + 16] = l;
                }
            } else {
                int c = o - 32;
                size_t base = ((size_t)b * CH + c) * NSP + n0 + tn * 4;
                #pragma unroll
                for (int p = 0; p < 2; ++p) {
                    float v0 = vals[2 * p], v1 = vals[2 * p + 1];
                    __nv_bfloat16 h0 = __float2bfloat16(v0);
                    __nv_bfloat16 h1 = __float2bfloat16(v1);
                    __nv_bfloat16 l0 = __float2bfloat16(v0 - __bfloat162float(h0));
                    __nv_bfloat16 l1 = __float2bfloat16(v1 - __bfloat162float(h1));
                    __nv_bfloat162 hp; hp.x = h0; hp.y = h1;
                    __nv_bfloat162 lp; lp.x = l0; lp.y = l1;
                    *(__nv_bfloat162*)(g_vh + base + 2 * p) = hp;
                    *(__nv_bfloat162*)(g_vl + base + 2 * p) = lp;
                }
            }
        }
    }
}

// ---------------------------------------------------------------------------
// HMMA flash attention. Block = (128-q i-tile, batch). 8 warps x 16 rows.
// ---------------------------------------------------------------------------
#define PI 132  // out staging pitch in f32

// smem byte offsets
#define OFF_Q    0
#define OFF_KS0  10240
#define OFF_VH0  15360
#define OFF_VL0  33792
#define OFF_KS1  52224
#define OFF_VH1  57344
#define OFF_VL1  75776
#define OFF_LRED 94208
#define SMEM_ATTN (94208 + 512)

__device__ __forceinline__ void prefetch_tile(int b, int j0,
                                              uint32_t ks, uint32_t vh, uint32_t vl,
                                              int tid)
{
    // K: 64 rows x 64 B
    {
        const char* kg = (const char*)(g_k2 + ((size_t)b * NSP + j0) * 32);
        int r = tid >> 2, ch = tid & 3;
        CP16(ks + (uint32_t)r * 80 + ch * 16, kg + (size_t)r * 64 + ch * 16);
    }
    // Vh/Vl: 128 rows x 128 B each
    const char* vhg = (const char*)(g_vh + (size_t)b * CH * NSP + j0);
    const char* vlg = (const char*)(g_vl + (size_t)b * CH * NSP + j0);
    #pragma unroll
    for (int u = 0; u < 4; ++u) {
        int m = tid + u * 256;
        int r = m >> 3, ch = m & 7;
        uint32_t doff = (uint32_t)r * 144 + ch * 16;
        size_t    soff = (size_t)r * (NSP * 2) + ch * 16;
        CP16(vh + doff, vhg + soff);
        CP16(vl + doff, vlg + soff);
    }
}

__global__ __launch_bounds__(256, 1) void attn_kernel(
    const float* __restrict__ x,
    const float* __restrict__ gamma,
    float* __restrict__ out)
{
    const uint32_t sb = smem_u32(dsmem);
    const int tid  = threadIdx.x;
    const int lane = tid & 31;
    const int wid  = tid >> 5;
    const int b    = blockIdx.y;
    const int i0   = blockIdx.x * TI;
    const int iw   = wid * 16;
    const int gid  = lane >> 2;
    const int m4   = lane & 3;

    const uint32_t KS[2] = {sb + OFF_KS0, sb + OFF_KS1};
    const uint32_t VH[2] = {sb + OFF_VH0, sb + OFF_VH1};
    const uint32_t VL[2] = {sb + OFF_VL0, sb + OFF_VL1};
    float* lred = (float*)(dsmem + OFF_LRED);
    float* outs = (float*)(dsmem + OFF_KS0);   // epilogue reuse

    // Load Q tile: 128 rows x 64 B -> pitch 80 B
    {
        const uint4* src = (const uint4*)(g_q2 + ((size_t)b * NSP + i0) * 32);
        #pragma unroll
        for (int u = 0; u < 2; ++u) {
            int m = tid + u * 256;
            int r = m >> 2, ch = m & 3;
            *(uint4*)(dsmem + OFF_Q + r * 80 + ch * 16) = src[m];
        }
    }
    prefetch_tile(b, 0, KS[0], VH[0], VL[0], tid);
    CPCOMMIT();
    __syncthreads();

    // Resident A-fragments of Q (hi and lo)
    uint32_t qh[4], ql[4];
    {
        uint32_t a = sb + OFF_Q + (uint32_t)(iw + (lane & 15)) * 80 + (lane >> 4) * 16;
        LDSM4(qh, a);
        LDSM4(ql, a + 32);
    }

    // ldmatrix address components for B operands (non-trans):
    // lanes 0-7: rows 0-7 (first k/j byte-half), 8-15: rows 0-7 (second half),
    // 16-23: rows 8-15 (first), 24-31: rows 8-15 (second)
    const int brow = (lane & 7) + ((lane >> 4) << 3);
    const int bcol = ((lane >> 3) & 1) * 8;

    float o[16][4];
    #pragma unroll
    for (int a = 0; a < 16; ++a)
        #pragma unroll
        for (int d = 0; d < 4; ++d) o[a][d] = 0.f;

    float lsum0 = 0.f, lsum1 = 0.f;

    for (int jt = 0; jt < NTJ; ++jt) {
        CPWAIT0();
        __syncthreads();
        if (jt + 1 < NTJ) {
            int ns = (jt + 1) & 1;
            prefetch_tile(b, (jt + 1) * TJ, KS[ns], VH[ns], VL[ns], tid);
            CPCOMMIT();
        }
        const int st = jt & 1;

        // ---- QK: S(16i x 64j) = qh*kh + qh*kl + ql*kh
        // B-frag = K[j][k] non-trans: matrix pair (j rows, k half 0/1) per n8 tile
        float sacc[8][4];
        #pragma unroll
        for (int a = 0; a < 8; ++a)
            #pragma unroll
            for (int d = 0; d < 4; ++d) sacc[a][d] = 0.f;

        #pragma unroll
        for (int combo = 0; combo < 3; ++combo) {
            const uint32_t* A = (combo == 2) ? ql : qh;
            const int kb = (combo == 1) ? 16 : 0;
            #pragma unroll
            for (int np = 0; np < 4; ++np) {
                uint32_t bK[4];
                LDSM4(bK, KS[st] + (uint32_t)(16 * np + brow) * 80 + (kb + bcol) * 2);
                MMA(sacc[2 * np],     A, bK);
                MMA(sacc[2 * np + 1], A, bK + 2);
            }
        }

        // ---- exp (FMA pipe) + bf16 hi/lo pack; P frags = A frags directly
        uint32_t ph[16], pl[16];
        #pragma unroll
        for (int a = 0; a < 8; ++a) {
            float p0 = fexp(sacc[a][0]);
            float p1 = fexp(sacc[a][1]);
            float p2 = fexp(sacc[a][2]);
            float p3 = fexp(sacc[a][3]);
            lsum0 += p0 + p1;
            lsum1 += p2 + p3;
            uint32_t h01 = packbf(p0, p1);
            uint32_t h23 = packbf(p2, p3);
            float l0 = p0 - __int_as_float((int)(h01 << 16));
            float l1 = p1 - __int_as_float((int)(h01 & 0xFFFF0000u));
            float l2 = p2 - __int_as_float((int)(h23 << 16));
            float l3 = p3 - __int_as_float((int)(h23 & 0xFFFF0000u));
            ph[2 * a]     = h01;
            ph[2 * a + 1] = h23;
            pl[2 * a]     = packbf(l0, l1);
            pl[2 * a + 1] = packbf(l2, l3);
        }

        // ---- PV: O(16i x 128c) += ph*vh + pl*vh + ph*vl
        // B-frag = V[c][j] non-trans: (c rows, j half) per c8 tile
        #pragma unroll
        for (int t4 = 0; t4 < 4; ++t4) {
            const uint32_t* ah = &ph[4 * t4];
            const uint32_t* al = &pl[4 * t4];
            #pragma unroll
            for (int p = 0; p < 8; ++p) {
                uint32_t roff = (uint32_t)(16 * p + brow) * 144 + (16 * t4 + bcol) * 2;
                uint32_t bh[4], bl[4];
                LDSM4(bh, VH[st] + roff);
                LDSM4(bl, VL[st] + roff);
                MMA(o[2 * p],     ah, bh);
                MMA(o[2 * p + 1], ah, bh + 2);
                MMA(o[2 * p],     al, bh);
                MMA(o[2 * p + 1], al, bh + 2);
                MMA(o[2 * p],     ah, bl);
                MMA(o[2 * p + 1], ah, bl + 2);
            }
        }
        __syncthreads();
    }

    // ---- l reduction (4 lanes per row hold partials)
    lsum0 += __shfl_xor_sync(0xFFFFFFFFu, lsum0, 1);
    lsum0 += __shfl_xor_sync(0xFFFFFFFFu, lsum0, 2);
    lsum1 += __shfl_xor_sync(0xFFFFFFFFu, lsum1, 1);
    lsum1 += __shfl_xor_sync(0xFFFFFFFFu, lsum1, 2);
    if (m4 == 0) {
        lred[iw + gid]     = lsum0;
        lred[iw + gid + 8] = lsum1;
    }
    __syncthreads();

    const float g = gamma[0];
    const float linv0 = g / lred[iw + gid];
    const float linv1 = g / lred[iw + gid + 8];

    // ---- stage scaled O to smem [c][i]
    #pragma unroll
    for (int a = 0; a < 16; ++a) {
        int c = 8 * a + 2 * m4;
        outs[c * PI + iw + gid]           = o[a][0] * linv0;
        outs[(c + 1) * PI + iw + gid]     = o[a][1] * linv0;
        outs[c * PI + iw + gid + 8]       = o[a][2] * linv1;
        outs[(c + 1) * PI + iw + gid + 8] = o[a][3] * linv1;
    }
    __syncthreads();

    // ---- residual fuse + store
    const float* xb = x + (size_t)(b * CH) * NSP + i0;
    float*       ob = out + (size_t)(b * CH) * NSP + i0;
    for (int m = tid; m < CH * 32; m += 256) {
        int c = m >> 5, i4 = (m & 31) * 4;
        float4 ov = *(const float4*)(outs + c * PI + i4);
        float4 xv = *(const float4*)(xb + (size_t)c * NSP + i4);
        ov.x += xv.x; ov.y += xv.y; ov.z += xv.z; ov.w += xv.w;
        *(float4*)(ob + (size_t)c * NSP + i4) = ov;
    }
}

// ---------------------------------------------------------------------------
extern "C" void kernel_launch(void* const* d_in, const int* in_sizes, int n_in,
                              void* d_out, int out_size)
{
    const float* x     = (const float*)d_in[0];
    const float* Wq    = (const float*)d_in[1];
    const float* bq    = (const float*)d_in[2];
    const float* Wk    = (const float*)d_in[3];
    const float* bk    = (const float*)d_in[4];
    const float* Wv    = (const float*)d_in[5];
    const float* bv    = (const float*)d_in[6];
    const float* gamma = (const float*)d_in[7];
    float* out = (float*)d_out;

    const size_t smem_proj = (CH * XS_PITCH + CH * WT_PITCH) * sizeof(float);

    cudaFuncSetAttribute(proj_kernel, cudaFuncAttributeMaxDynamicSharedMemorySize,
                         (int)smem_proj);
    cudaFuncSetAttribute(attn_kernel, cudaFuncAttributeMaxDynamicSharedMemorySize,
                         SMEM_ATTN);

    dim3 gp(NSP / 64, BATCH);        // (64, 4)
    proj_kernel<<<gp, 256, smem_proj>>>(x, Wq, bq, Wk, bk, Wv, bv);

    dim3 ga(NSP / TI, BATCH);        // (32, 4) = 128 blocks
    attn_kernel<<<ga, 256, SMEM_ATTN>>>(x, gamma, out);
}

// round 8
// speedup vs baseline: 6.1715x; 1.5946x over previous
#include <cuda_runtime.h>
#include <cuda_fp16.h>
#include <cstdint>
#include <math.h>

#define BATCH 4
#define CH    128
#define C8    16
#define NSP   4096
#define CO    160
#define TI    128
#define TJ    64
#define NTJ   (NSP / TJ)

// f16 operands produced by proj kernel
__device__ __align__(16) __half g_q2[BATCH * NSP * 32];  // [b][n][ qh(16) | ql(16) ]
__device__ __align__(16) __half g_k2[BATCH * NSP * 32];  // [b][n][ kh(16) | kl(16) ]
__device__ __align__(16) __half g_v [BATCH * CH * NSP];  // [b][c][n] single f16

extern __shared__ __align__(16) char dsmem[];

// ---------------------------------------------------------------------------
// helpers
// ---------------------------------------------------------------------------
__device__ __forceinline__ uint32_t smem_u32(const void* p) {
    uint32_t a;
    asm("{ .reg .u64 t; cvta.to.shared.u64 t, %1; cvt.u32.u64 %0, t; }"
        : "=r"(a) : "l"(p));
    return a;
}

#define LDSM4(r, addr) \
    asm volatile("ldmatrix.sync.aligned.m8n8.x4.shared.b16 {%0,%1,%2,%3}, [%4];" \
        : "=r"((r)[0]), "=r"((r)[1]), "=r"((r)[2]), "=r"((r)[3]) : "r"(addr))

// D(+=) = A(m16k16 f16) * B(k16n8 f16), f32 accum
#define MMAH(d, a, b) \
    asm volatile("mma.sync.aligned.m16n8k16.row.col.f32.f16.f16.f32 " \
        "{%0,%1,%2,%3}, {%4,%5,%6,%7}, {%8,%9}, {%0,%1,%2,%3};" \
        : "+f"((d)[0]), "+f"((d)[1]), "+f"((d)[2]), "+f"((d)[3]) \
        : "r"((a)[0]), "r"((a)[1]), "r"((a)[2]), "r"((a)[3]), \
          "r"((b)[0]), "r"((b)[1]))

#define CP16(dst, src) \
    asm volatile("cp.async.cg.shared.global [%0], [%1], 16;" :: "r"(dst), "l"(src))
#define CPCOMMIT() asm volatile("cp.async.commit_group;" ::: "memory")
#define CPWAIT0()  asm volatile("cp.async.wait_group 0;" ::: "memory")

// exp(d) for d <= 0, FMA pipe only: 2^t via magic rounding, degree-5 Taylor,
// t clamped at -120 so the exponent bit-trick never wraps.
__device__ __forceinline__ float fexpc(float d) {
    float t  = d * 1.4426950408889634f;
    t = fmaxf(t, -120.f);
    float z  = t + 12582912.f;                    // 1.5*2^23, round-to-nearest
    float fl = z - 12582912.f;
    float f  = t - fl;                            // f in [-0.5, 0.5]
    float p  =              1.3333558146e-3f;
    p = fmaf(p, f, 9.6181291076e-3f);
    p = fmaf(p, f, 5.5504108664e-2f);
    p = fmaf(p, f, 2.4022650696e-1f);
    p = fmaf(p, f, 6.9314718056e-1f);
    p = fmaf(p, f, 1.0f);
    float sc = __int_as_float((__float_as_int(z) << 23) + 0x3F800000);
    return p * sc;
}

__device__ __forceinline__ uint32_t packh2(float lo, float hi) {
    __half2 h = __floats2half2_rn(lo, hi);  // lo -> low 16 bits
    return *reinterpret_cast<uint32_t*>(&h);
}

// ---------------------------------------------------------------------------
// Projection: [q;k;v](160,N) = W @ x + b. One pass per blockIdx.z.
// ---------------------------------------------------------------------------
#define XS_PITCH 68
#define WT_PITCH 65

__global__ __launch_bounds__(256) void proj_kernel(
    const float* __restrict__ x,
    const float* __restrict__ Wq, const float* __restrict__ bq,
    const float* __restrict__ Wk, const float* __restrict__ bk,
    const float* __restrict__ Wv, const float* __restrict__ bv)
{
    float* xs = (float*)dsmem;             // [128][68]
    float* Wt = xs + CH * XS_PITCH;        // [128][65]

    const int t    = threadIdx.x;
    const int b    = blockIdx.y;
    const int n0   = blockIdx.x * 64;
    const int pass = blockIdx.z;

    const float* xb = x + (size_t)(b * CH) * NSP + n0;
    for (int idx4 = t; idx4 < CH * 16; idx4 += 256) {
        int c  = idx4 >> 4;
        int nq = idx4 & 15;
        float4 v = *(const float4*)(xb + (size_t)c * NSP + nq * 4);
        *(float4*)(xs + c * XS_PITCH + nq * 4) = v;
    }
    for (int idx = t; idx < 64 * CH; idx += 256) {
        int ol = idx >> 7;
        int c  = idx & 127;
        int o  = pass * 64 + ol;
        float w = 0.f;
        if (o < 16)       w = Wq[o * CH + c];
        else if (o < 32)  w = Wk[(o - 16) * CH + c];
        else if (o < CO)  w = Wv[(o - 32) * CH + c];
        Wt[c * WT_PITCH + ol] = w;
    }
    __syncthreads();

    const int tn  = t & 15;
    const int to  = t >> 4;
    const int olb = to * 4;

    float acc[4][4];
    #pragma unroll
    for (int a = 0; a < 4; ++a)
        #pragma unroll
        for (int d = 0; d < 4; ++d) acc[a][d] = 0.f;

    #pragma unroll 4
    for (int c = 0; c < CH; ++c) {
        const float* wr = Wt + c * WT_PITCH + olb;
        float wa[4] = {wr[0], wr[1], wr[2], wr[3]};
        float4 xv = *(const float4*)(xs + c * XS_PITCH + tn * 4);
        float xa[4] = {xv.x, xv.y, xv.z, xv.w};
        #pragma unroll
        for (int a = 0; a < 4; ++a)
            #pragma unroll
            for (int d = 0; d < 4; ++d)
                acc[a][d] = fmaf(wa[a], xa[d], acc[a][d]);
    }

    #pragma unroll
    for (int oo = 0; oo < 4; ++oo) {
        int o = pass * 64 + olb + oo;
        if (o >= CO) continue;
        float bb;
        if (o < 16)       bb = bq[o];
        else if (o < 32)  bb = bk[o - 16];
        else              bb = bv[o - 32];
        float vals[4];
        #pragma unroll
        for (int d = 0; d < 4; ++d) vals[d] = acc[oo][d] + bb;

        if (o < 32) {
            __half* dst = (o < 16) ? g_q2 : g_k2;
            int oc = (o < 16) ? o : (o - 16);
            #pragma unroll
            for (int d = 0; d < 4; ++d) {
                int n = n0 + tn * 4 + d;
                float v = vals[d];
                __half h = __float2half_rn(v);
                __half l = __float2half_rn(v - __half2float(h));
                size_t base = ((size_t)b * NSP + n) * 32;
                dst[base + oc]      = h;
                dst[base + oc + 16] = l;
            }
        } else {
            int c = o - 32;
            size_t base = ((size_t)b * CH + c) * NSP + n0 + tn * 4;
            #pragma unroll
            for (int p = 0; p < 2; ++p) {
                __half2 hp = __floats2half2_rn(vals[2 * p], vals[2 * p + 1]);
                *(__half2*)(g_v + base + 2 * p) = hp;
            }
        }
    }
}

// ---------------------------------------------------------------------------
// HMMA flash attention, f16 with online softmax. 8 warps x 16 rows.
// ---------------------------------------------------------------------------
#define PI 132  // out staging pitch in f32

// smem byte offsets
#define OFF_Q    0
#define OFF_KS0  10240
#define OFF_V0   15360
#define OFF_KS1  33792
#define OFF_V1   38912
#define OFF_LRED 77824
#define SMEM_ATTN (77824 + 2048)

__device__ __forceinline__ void prefetch_tile(int b, int j0,
                                              uint32_t ks, uint32_t vs, int tid)
{
    // K: 64 rows x 64 B
    {
        const char* kg = (const char*)(g_k2 + ((size_t)b * NSP + j0) * 32);
        int r = tid >> 2, ch = tid & 3;
        CP16(ks + (uint32_t)r * 80 + ch * 16, kg + (size_t)r * 64 + ch * 16);
    }
    // V: 128 rows (c) x 128 B (64 f16 j)
    const char* vg = (const char*)(g_v + (size_t)b * CH * NSP + j0);
    #pragma unroll
    for (int u = 0; u < 4; ++u) {
        int m = tid + u * 256;
        int r = m >> 3, ch = m & 7;
        CP16(vs + (uint32_t)r * 144 + ch * 16, vg + (size_t)r * (NSP * 2) + ch * 16);
    }
}

__global__ __launch_bounds__(256, 1) void attn_kernel(
    const float* __restrict__ x,
    const float* __restrict__ gamma,
    float* __restrict__ out)
{
    const uint32_t sb = smem_u32(dsmem);
    const int tid  = threadIdx.x;
    const int lane = tid & 31;
    const int wid  = tid >> 5;
    const int b    = blockIdx.y;
    const int i0   = blockIdx.x * TI;
    const int iw   = wid * 16;
    const int gid  = lane >> 2;
    const int m4   = lane & 3;

    const uint32_t KS[2] = {sb + OFF_KS0, sb + OFF_KS1};
    const uint32_t VS[2] = {sb + OFF_V0,  sb + OFF_V1};
    float* lred = (float*)(dsmem + OFF_LRED);
    float* outs = (float*)(dsmem + OFF_KS0);   // epilogue reuse

    // Load Q tile: 128 rows x 64 B -> pitch 80 B
    {
        const uint4* src = (const uint4*)(g_q2 + ((size_t)b * NSP + i0) * 32);
        #pragma unroll
        for (int u = 0; u < 2; ++u) {
            int m = tid + u * 256;
            int r = m >> 2, ch = m & 3;
            *(uint4*)(dsmem + OFF_Q + r * 80 + ch * 16) = src[m];
        }
    }
    prefetch_tile(b, 0, KS[0], VS[0], tid);
    CPCOMMIT();
    __syncthreads();

    // Resident A-fragments of Q (hi and lo)
    uint32_t qh[4], ql[4];
    {
        uint32_t a = sb + OFF_Q + (uint32_t)(iw + (lane & 15)) * 80 + (lane >> 4) * 16;
        LDSM4(qh, a);
        LDSM4(ql, a + 32);
    }

    // ldmatrix address components for B operands (non-trans)
    const int brow = (lane & 7) + ((lane >> 4) << 3);
    const int bcol = ((lane >> 3) & 1) * 8;

    float o[16][4];
    #pragma unroll
    for (int a = 0; a < 16; ++a)
        #pragma unroll
        for (int d = 0; d < 4; ++d) o[a][d] = 0.f;

    float lsum0 = 0.f, lsum1 = 0.f;
    float m0 = -60.f, m1 = -60.f;    // running row maxes (safe floor)

    for (int jt = 0; jt < NTJ; ++jt) {
        CPWAIT0();
        __syncthreads();
        if (jt + 1 < NTJ) {
            int ns = (jt + 1) & 1;
            prefetch_tile(b, (jt + 1) * TJ, KS[ns], VS[ns], tid);
            CPCOMMIT();
        }
        const int st = jt & 1;

        // ---- QK: S(16i x 64j) = qh*kh + ql*kh + qh*kl  (kh frags reused)
        float sacc[8][4];
        #pragma unroll
        for (int a = 0; a < 8; ++a)
            #pragma unroll
            for (int d = 0; d < 4; ++d) sacc[a][d] = 0.f;

        #pragma unroll
        for (int np = 0; np < 4; ++np) {
            uint32_t base = KS[st] + (uint32_t)(16 * np + brow) * 80 + bcol * 2;
            uint32_t bKh[4], bKl[4];
            LDSM4(bKh, base);
            LDSM4(bKl, base + 32);
            MMAH(sacc[2 * np],     qh, bKh);
            MMAH(sacc[2 * np + 1], qh, bKh + 2);
            MMAH(sacc[2 * np],     ql, bKh);
            MMAH(sacc[2 * np + 1], ql, bKh + 2);
            MMAH(sacc[2 * np],     qh, bKl);
            MMAH(sacc[2 * np + 1], qh, bKl + 2);
        }

        // ---- online softmax: row max over this tile (rows live in lane quads)
        float tm0 = -1e30f, tm1 = -1e30f;
        #pragma unroll
        for (int a = 0; a < 8; ++a) {
            tm0 = fmaxf(tm0, fmaxf(sacc[a][0], sacc[a][1]));
            tm1 = fmaxf(tm1, fmaxf(sacc[a][2], sacc[a][3]));
        }
        tm0 = fmaxf(tm0, __shfl_xor_sync(0xFFFFFFFFu, tm0, 1));
        tm0 = fmaxf(tm0, __shfl_xor_sync(0xFFFFFFFFu, tm0, 2));
        tm1 = fmaxf(tm1, __shfl_xor_sync(0xFFFFFFFFu, tm1, 1));
        tm1 = fmaxf(tm1, __shfl_xor_sync(0xFFFFFFFFu, tm1, 2));

        const float mn0 = fmaxf(m0, tm0);
        const float mn1 = fmaxf(m1, tm1);
        const float sc0 = fexpc(m0 - mn0);
        const float sc1 = fexpc(m1 - mn1);
        m0 = mn0; m1 = mn1;
        lsum0 *= sc0;
        lsum1 *= sc1;
        // Rescale O only if some row max moved (rare after early tiles)
        if (__any_sync(0xFFFFFFFFu, (sc0 < 1.f) || (sc1 < 1.f))) {
            #pragma unroll
            for (int a = 0; a < 16; ++a) {
                o[a][0] *= sc0; o[a][1] *= sc0;
                o[a][2] *= sc1; o[a][3] *= sc1;
            }
        }

        // ---- p = exp(s - m) in (0,1], pack straight to f16 A-fragments
        uint32_t ph[16];
        #pragma unroll
        for (int a = 0; a < 8; ++a) {
            float p0 = fexpc(sacc[a][0] - mn0);
            float p1 = fexpc(sacc[a][1] - mn0);
            float p2 = fexpc(sacc[a][2] - mn1);
            float p3 = fexpc(sacc[a][3] - mn1);
            lsum0 += p0 + p1;
            lsum1 += p2 + p3;
            ph[2 * a]     = packh2(p0, p1);
            ph[2 * a + 1] = packh2(p2, p3);
        }

        // ---- PV: O(16i x 128c) += P(f16) * V(f16)
        #pragma unroll
        for (int t4 = 0; t4 < 4; ++t4) {
            const uint32_t* A = &ph[4 * t4];
            #pragma unroll
            for (int p = 0; p < 8; ++p) {
                uint32_t bv[4];
                LDSM4(bv, VS[st] + (uint32_t)(16 * p + brow) * 144 + (16 * t4 + bcol) * 2);
                MMAH(o[2 * p],     A, bv);
                MMAH(o[2 * p + 1], A, bv + 2);
            }
        }
    }

    // ---- l reduction (4 lanes per row hold partials)
    lsum0 += __shfl_xor_sync(0xFFFFFFFFu, lsum0, 1);
    lsum0 += __shfl_xor_sync(0xFFFFFFFFu, lsum0, 2);
    lsum1 += __shfl_xor_sync(0xFFFFFFFFu, lsum1, 1);
    lsum1 += __shfl_xor_sync(0xFFFFFFFFu, lsum1, 2);
    if (m4 == 0) {
        lred[iw + gid]     = lsum0;
        lred[iw + gid + 8] = lsum1;
    }
    __syncthreads();   // also: all PV reads of V buffers complete past here

    const float g = gamma[0];
    const float linv0 = g / lred[iw + gid];
    const float linv1 = g / lred[iw + gid + 8];

    // ---- stage scaled O to smem [c][i]
    #pragma unroll
    for (int a = 0; a < 16; ++a) {
        int c = 8 * a + 2 * m4;
        outs[c * PI + iw + gid]           = o[a][0] * linv0;
        outs[(c + 1) * PI + iw + gid]     = o[a][1] * linv0;
        outs[c * PI + iw + gid + 8]       = o[a][2] * linv1;
        outs[(c + 1) * PI + iw + gid + 8] = o[a][3] * linv1;
    }
    __syncthreads();

    // ---- residual fuse + store
    const float* xb = x + (size_t)(b * CH) * NSP + i0;
    float*       ob = out + (size_t)(b * CH) * NSP + i0;
    for (int m = tid; m < CH * 32; m += 256) {
        int c = m >> 5, i4 = (m & 31) * 4;
        float4 ov = *(const float4*)(outs + c * PI + i4);
        float4 xv = *(const float4*)(xb + (size_t)c * NSP + i4);
        ov.x += xv.x; ov.y += xv.y; ov.z += xv.z; ov.w += xv.w;
        *(float4*)(ob + (size_t)c * NSP + i4) = ov;
    }
}

// ---------------------------------------------------------------------------
extern "C" void kernel_launch(void* const* d_in, const int* in_sizes, int n_in,
                              void* d_out, int out_size)
{
    const float* x     = (const float*)d_in[0];
    const float* Wq    = (const float*)d_in[1];
    const float* bq    = (const float*)d_in[2];
    const float* Wk    = (const float*)d_in[3];
    const float* bk    = (const float*)d_in[4];
    const float* Wv    = (const float*)d_in[5];
    const float* bv    = (const float*)d_in[6];
    const float* gamma = (const float*)d_in[7];
    float* out = (float*)d_out;

    const size_t smem_proj = (CH * XS_PITCH + CH * WT_PITCH) * sizeof(float);

    cudaFuncSetAttribute(proj_kernel, cudaFuncAttributeMaxDynamicSharedMemorySize,
                         (int)smem_proj);
    cudaFuncSetAttribute(attn_kernel, cudaFuncAttributeMaxDynamicSharedMemorySize,
                         SMEM_ATTN);

    dim3 gp(NSP / 64, BATCH, 3);     // (64, 4, 3) = 768 blocks, one pass each
    proj_kernel<<<gp, 256, smem_proj>>>(x, Wq, bq, Wk, bk, Wv, bv);

    dim3 ga(NSP / TI, BATCH);        // (32, 4) = 128 blocks
    attn_kernel<<<ga, 256, SMEM_ATTN>>>(x, gamma, out);
}

// round 9
// speedup vs baseline: 7.0348x; 1.1399x over previous
#include <cuda_runtime.h>
#include <cuda_fp16.h>
#include <cstdint>
#include <math.h>

#define BATCH 4
#define CH    128
#define C8    16
#define NSP   4096
#define CO    160
#define TI    64
#define TJ    64
#define NTJ   (NSP / TJ)

// f16 operands produced by proj kernel
__device__ __align__(16) __half g_q2[BATCH * NSP * 32];  // [b][n][ qh(16) | ql(16) ]
__device__ __align__(16) __half g_k2[BATCH * NSP * 32];  // [b][n][ kh(16) | kl(16) ]
__device__ __align__(16) __half g_v [BATCH * CH * NSP];  // [b][c][n] single f16

extern __shared__ __align__(16) char dsmem[];

// ---------------------------------------------------------------------------
// helpers
// ---------------------------------------------------------------------------
__device__ __forceinline__ uint32_t smem_u32(const void* p) {
    uint32_t a;
    asm("{ .reg .u64 t; cvta.to.shared.u64 t, %1; cvt.u32.u64 %0, t; }"
        : "=r"(a) : "l"(p));
    return a;
}

#define LDSM4(r, addr) \
    asm volatile("ldmatrix.sync.aligned.m8n8.x4.shared.b16 {%0,%1,%2,%3}, [%4];" \
        : "=r"((r)[0]), "=r"((r)[1]), "=r"((r)[2]), "=r"((r)[3]) : "r"(addr))

// D(+=) = A(m16k16 f16) * B(k16n8 f16), f32 accum
#define MMAH(d, a, b) \
    asm volatile("mma.sync.aligned.m16n8k16.row.col.f32.f16.f16.f32 " \
        "{%0,%1,%2,%3}, {%4,%5,%6,%7}, {%8,%9}, {%0,%1,%2,%3};" \
        : "+f"((d)[0]), "+f"((d)[1]), "+f"((d)[2]), "+f"((d)[3]) \
        : "r"((a)[0]), "r"((a)[1]), "r"((a)[2]), "r"((a)[3]), \
          "r"((b)[0]), "r"((b)[1]))

#define CP16(dst, src) \
    asm volatile("cp.async.cg.shared.global [%0], [%1], 16;" :: "r"(dst), "l"(src))
#define CPCOMMIT() asm volatile("cp.async.commit_group;" ::: "memory")
#define CPWAIT0()  asm volatile("cp.async.wait_group 0;" ::: "memory")

#define LOG2E 1.4426950408889634f

// 2^t on the SFU pipe (MUFU.EX2) — keeps the FMA pipe free for MMA-adjacent work
__device__ __forceinline__ float fex2(float t) {
    float r;
    asm("ex2.approx.f32 %0, %1;" : "=f"(r) : "f"(t));
    return r;
}

__device__ __forceinline__ uint32_t packh2(float lo, float hi) {
    __half2 h = __floats2half2_rn(lo, hi);  // lo -> low 16 bits
    return *reinterpret_cast<uint32_t*>(&h);
}

// ---------------------------------------------------------------------------
// Projection: [q;k;v](160,N) = W @ x + b. One pass per blockIdx.z.
// ---------------------------------------------------------------------------
#define XS_PITCH 68
#define WT_PITCH 68

__global__ __launch_bounds__(256) void proj_kernel(
    const float* __restrict__ x,
    const float* __restrict__ Wq, const float* __restrict__ bq,
    const float* __restrict__ Wk, const float* __restrict__ bk,
    const float* __restrict__ Wv, const float* __restrict__ bv)
{
    float* xs = (float*)dsmem;             // [128][68]
    float* Wt = xs + CH * XS_PITCH;        // [128][68]

    const int t    = threadIdx.x;
    const int b    = blockIdx.y;
    const int n0   = blockIdx.x * 64;
    const int pass = blockIdx.z;

    const float* xb = x + (size_t)(b * CH) * NSP + n0;
    for (int idx4 = t; idx4 < CH * 16; idx4 += 256) {
        int c  = idx4 >> 4;
        int nq = idx4 & 15;
        float4 v = *(const float4*)(xb + (size_t)c * NSP + nq * 4);
        *(float4*)(xs + c * XS_PITCH + nq * 4) = v;
    }
    for (int idx = t; idx < 64 * CH; idx += 256) {
        int ol = idx >> 7;
        int c  = idx & 127;
        int o  = pass * 64 + ol;
        float w = 0.f;
        if (o < 16)       w = Wq[o * CH + c];
        else if (o < 32)  w = Wk[(o - 16) * CH + c];
        else if (o < CO)  w = Wv[(o - 32) * CH + c];
        Wt[c * WT_PITCH + ol] = w;
    }
    __syncthreads();

    const int tn  = t & 15;
    const int to  = t >> 4;
    const int olb = to * 4;

    float acc[4][4];
    #pragma unroll
    for (int a = 0; a < 4; ++a)
        #pragma unroll
        for (int d = 0; d < 4; ++d) acc[a][d] = 0.f;

    #pragma unroll 4
    for (int c = 0; c < CH; ++c) {
        float4 wv = *(const float4*)(Wt + c * WT_PITCH + olb);
        float4 xv = *(const float4*)(xs + c * XS_PITCH + tn * 4);
        float wa[4] = {wv.x, wv.y, wv.z, wv.w};
        float xa[4] = {xv.x, xv.y, xv.z, xv.w};
        #pragma unroll
        for (int a = 0; a < 4; ++a)
            #pragma unroll
            for (int d = 0; d < 4; ++d)
                acc[a][d] = fmaf(wa[a], xa[d], acc[a][d]);
    }

    #pragma unroll
    for (int oo = 0; oo < 4; ++oo) {
        int o = pass * 64 + olb + oo;
        if (o >= CO) continue;
        float bb;
        if (o < 16)       bb = bq[o];
        else if (o < 32)  bb = bk[o - 16];
        else              bb = bv[o - 32];
        float vals[4];
        #pragma unroll
        for (int d = 0; d < 4; ++d) vals[d] = acc[oo][d] + bb;

        if (o < 32) {
            __half* dst = (o < 16) ? g_q2 : g_k2;
            int oc = (o < 16) ? o : (o - 16);
            #pragma unroll
            for (int d = 0; d < 4; ++d) {
                int n = n0 + tn * 4 + d;
                float v = vals[d];
                __half h = __float2half_rn(v);
                __half l = __float2half_rn(v - __half2float(h));
                size_t base = ((size_t)b * NSP + n) * 32;
                dst[base + oc]      = h;
                dst[base + oc + 16] = l;
            }
        } else {
            int c = o - 32;
            size_t base = ((size_t)b * CH + c) * NSP + n0 + tn * 4;
            #pragma unroll
            for (int p = 0; p < 2; ++p) {
                __half2 hp = __floats2half2_rn(vals[2 * p], vals[2 * p + 1]);
                *(__half2*)(g_v + base + 2 * p) = hp;
            }
        }
    }
}

// ---------------------------------------------------------------------------
// HMMA flash attention, f16, online softmax. 64-q CTA, 4 warps, 2 CTAs/SM.
// ---------------------------------------------------------------------------
#define PI 68   // out staging pitch in f32

// smem byte offsets (per CTA: 52.7 KB -> 2 CTAs/SM)
#define OFF_Q    0
#define OFF_KS0  5120
#define OFF_V0   10240
#define OFF_KS1  28672
#define OFF_V1   33792
#define OFF_LRED 52224
#define SMEM_ATTN (52224 + 512)

__device__ __forceinline__ void prefetch_tile(int b, int j0,
                                              uint32_t ks, uint32_t vs, int tid)
{
    // K: 64 rows x 64 B -> pitch 80 B
    {
        const char* kg = (const char*)(g_k2 + ((size_t)b * NSP + j0) * 32);
        #pragma unroll
        for (int u = 0; u < 2; ++u) {
            int m = tid + u * 128;
            int r = m >> 2, ch = m & 3;
            CP16(ks + (uint32_t)r * 80 + ch * 16, kg + (size_t)r * 64 + ch * 16);
        }
    }
    // V: 128 rows (c) x 128 B (64 f16 j) -> pitch 144 B
    const char* vg = (const char*)(g_v + (size_t)b * CH * NSP + j0);
    #pragma unroll
    for (int u = 0; u < 8; ++u) {
        int m = tid + u * 128;
        int r = m >> 3, ch = m & 7;
        CP16(vs + (uint32_t)r * 144 + ch * 16, vg + (size_t)r * (NSP * 2) + ch * 16);
    }
}

__global__ __launch_bounds__(128, 2) void attn_kernel(
    const float* __restrict__ x,
    const float* __restrict__ gamma,
    float* __restrict__ out)
{
    const uint32_t sb = smem_u32(dsmem);
    const int tid  = threadIdx.x;
    const int lane = tid & 31;
    const int wid  = tid >> 5;
    const int b    = blockIdx.y;
    const int i0   = blockIdx.x * TI;
    const int iw   = wid * 16;
    const int gid  = lane >> 2;
    const int m4   = lane & 3;

    const uint32_t KS[2] = {sb + OFF_KS0, sb + OFF_KS1};
    const uint32_t VS[2] = {sb + OFF_V0,  sb + OFF_V1};
    float* lred = (float*)(dsmem + OFF_LRED);
    float* outs = (float*)(dsmem + OFF_KS0);   // epilogue reuse (34.8 KB fits)

    // Load Q tile: 64 rows x 64 B -> pitch 80 B
    {
        const uint4* src = (const uint4*)(g_q2 + ((size_t)b * NSP + i0) * 32);
        #pragma unroll
        for (int u = 0; u < 2; ++u) {
            int m = tid + u * 128;
            int r = m >> 2, ch = m & 3;
            *(uint4*)(dsmem + OFF_Q + r * 80 + ch * 16) = src[m];
        }
    }
    prefetch_tile(b, 0, KS[0], VS[0], tid);
    CPCOMMIT();
    __syncthreads();

    // Resident A-fragments of Q (hi and lo)
    uint32_t qh[4], ql[4];
    {
        uint32_t a = sb + OFF_Q + (uint32_t)(iw + (lane & 15)) * 80 + (lane >> 4) * 16;
        LDSM4(qh, a);
        LDSM4(ql, a + 32);
    }

    // ldmatrix address components for B operands (non-trans)
    const int brow = (lane & 7) + ((lane >> 4) << 3);
    const int bcol = ((lane >> 3) & 1) * 8;

    float o[16][4];
    #pragma unroll
    for (int a = 0; a < 16; ++a)
        #pragma unroll
        for (int d = 0; d < 4; ++d) o[a][d] = 0.f;

    float lsum0 = 0.f, lsum1 = 0.f;
    float m0 = -60.f, m1 = -60.f;    // running row maxes (safe floor)

    for (int jt = 0; jt < NTJ; ++jt) {
        CPWAIT0();
        __syncthreads();
        if (jt + 1 < NTJ) {
            int ns = (jt + 1) & 1;
            prefetch_tile(b, (jt + 1) * TJ, KS[ns], VS[ns], tid);
            CPCOMMIT();
        }
        const int st = jt & 1;

        // ---- QK: S(16i x 64j) = qh*kh + ql*kh + qh*kl  (kh frags reused)
        float sacc[8][4];
        #pragma unroll
        for (int a = 0; a < 8; ++a)
            #pragma unroll
            for (int d = 0; d < 4; ++d) sacc[a][d] = 0.f;

        #pragma unroll
        for (int np = 0; np < 4; ++np) {
            uint32_t base = KS[st] + (uint32_t)(16 * np + brow) * 80 + bcol * 2;
            uint32_t bKh[4], bKl[4];
            LDSM4(bKh, base);
            LDSM4(bKl, base + 32);
            MMAH(sacc[2 * np],     qh, bKh);
            MMAH(sacc[2 * np + 1], qh, bKh + 2);
            MMAH(sacc[2 * np],     ql, bKh);
            MMAH(sacc[2 * np + 1], ql, bKh + 2);
            MMAH(sacc[2 * np],     qh, bKl);
            MMAH(sacc[2 * np + 1], qh, bKl + 2);
        }

        // ---- online softmax: row max over this tile (rows live in lane quads)
        float tm0 = -1e30f, tm1 = -1e30f;
        #pragma unroll
        for (int a = 0; a < 8; ++a) {
            tm0 = fmaxf(tm0, fmaxf(sacc[a][0], sacc[a][1]));
            tm1 = fmaxf(tm1, fmaxf(sacc[a][2], sacc[a][3]));
        }
        tm0 = fmaxf(tm0, __shfl_xor_sync(0xFFFFFFFFu, tm0, 1));
        tm0 = fmaxf(tm0, __shfl_xor_sync(0xFFFFFFFFu, tm0, 2));
        tm1 = fmaxf(tm1, __shfl_xor_sync(0xFFFFFFFFu, tm1, 1));
        tm1 = fmaxf(tm1, __shfl_xor_sync(0xFFFFFFFFu, tm1, 2));

        const float mn0 = fmaxf(m0, tm0);
        const float mn1 = fmaxf(m1, tm1);
        const float sc0 = fex2((m0 - mn0) * LOG2E);
        const float sc1 = fex2((m1 - mn1) * LOG2E);
        m0 = mn0; m1 = mn1;
        lsum0 *= sc0;
        lsum1 *= sc1;
        // Rescale O only if some row max moved (rare after early tiles)
        if (__any_sync(0xFFFFFFFFu, (sc0 < 1.f) || (sc1 < 1.f))) {
            #pragma unroll
            for (int a = 0; a < 16; ++a) {
                o[a][0] *= sc0; o[a][1] *= sc0;
                o[a][2] *= sc1; o[a][3] *= sc1;
            }
        }

        // ---- p = exp(s - m) in (0,1] on the MUFU pipe; pack to f16 A-frags
        const float c0 = -mn0 * LOG2E;
        const float c1 = -mn1 * LOG2E;
        uint32_t ph[16];
        #pragma unroll
        for (int a = 0; a < 8; ++a) {
            float p0 = fex2(fmaf(sacc[a][0], LOG2E, c0));
            float p1 = fex2(fmaf(sacc[a][1], LOG2E, c0));
            float p2 = fex2(fmaf(sacc[a][2], LOG2E, c1));
            float p3 = fex2(fmaf(sacc[a][3], LOG2E, c1));
            lsum0 += p0 + p1;
            lsum1 += p2 + p3;
            ph[2 * a]     = packh2(p0, p1);
            ph[2 * a + 1] = packh2(p2, p3);
        }

        // ---- PV: O(16i x 128c) += P(f16) * V(f16)
        #pragma unroll
        for (int t4 = 0; t4 < 4; ++t4) {
            const uint32_t* A = &ph[4 * t4];
            #pragma unroll
            for (int p = 0; p < 8; ++p) {
                uint32_t bv[4];
                LDSM4(bv, VS[st] + (uint32_t)(16 * p + brow) * 144 + (16 * t4 + bcol) * 2);
                MMAH(o[2 * p],     A, bv);
                MMAH(o[2 * p + 1], A, bv + 2);
            }
        }
    }

    // ---- l reduction (4 lanes per row hold partials)
    lsum0 += __shfl_xor_sync(0xFFFFFFFFu, lsum0, 1);
    lsum0 += __shfl_xor_sync(0xFFFFFFFFu, lsum0, 2);
    lsum1 += __shfl_xor_sync(0xFFFFFFFFu, lsum1, 1);
    lsum1 += __shfl_xor_sync(0xFFFFFFFFu, lsum1, 2);
    if (m4 == 0) {
        lred[iw + gid]     = lsum0;
        lred[iw + gid + 8] = lsum1;
    }
    __syncthreads();   // also: all PV reads of V buffers complete past here

    const float g = gamma[0];
    const float linv0 = g / lred[iw + gid];
    const float linv1 = g / lred[iw + gid + 8];

    // ---- stage scaled O to smem [c][i]
    #pragma unroll
    for (int a = 0; a < 16; ++a) {
        int c = 8 * a + 2 * m4;
        outs[c * PI + iw + gid]           = o[a][0] * linv0;
        outs[(c + 1) * PI + iw + gid]     = o[a][1] * linv0;
        outs[c * PI + iw + gid + 8]       = o[a][2] * linv1;
        outs[(c + 1) * PI + iw + gid + 8] = o[a][3] * linv1;
    }
    __syncthreads();

    // ---- residual fuse + store
    const float* xb = x + (size_t)(b * CH) * NSP + i0;
    float*       ob = out + (size_t)(b * CH) * NSP + i0;
    for (int m = tid; m < CH * (TI / 4); m += 128) {
        int c = m >> 4, i4 = (m & 15) * 4;
        float4 ov = *(const float4*)(outs + c * PI + i4);
        float4 xv = *(const float4*)(xb + (size_t)c * NSP + i4);
        ov.x += xv.x; ov.y += xv.y; ov.z += xv.z; ov.w += xv.w;
        *(float4*)(ob + (size_t)c * NSP + i4) = ov;
    }
}

// ---------------------------------------------------------------------------
extern "C" void kernel_launch(void* const* d_in, const int* in_sizes, int n_in,
                              void* d_out, int out_size)
{
    const float* x     = (const float*)d_in[0];
    const float* Wq    = (const float*)d_in[1];
    const float* bq    = (const float*)d_in[2];
    const float* Wk    = (const float*)d_in[3];
    const float* bk    = (const float*)d_in[4];
    const float* Wv    = (const float*)d_in[5];
    const float* bv    = (const float*)d_in[6];
    const float* gamma = (const float*)d_in[7];
    float* out = (float*)d_out;

    const size_t smem_proj = (CH * XS_PITCH + CH * WT_PITCH) * sizeof(float);

    cudaFuncSetAttribute(proj_kernel, cudaFuncAttributeMaxDynamicSharedMemorySize,
                         (int)smem_proj);
    cudaFuncSetAttribute(attn_kernel, cudaFuncAttributeMaxDynamicSharedMemorySize,
                         SMEM_ATTN);

    dim3 gp(NSP / 64, BATCH, 3);     // (64, 4, 3) = 768 blocks, one pass each
    proj_kernel<<<gp, 256, smem_proj>>>(x, Wq, bq, Wk, bk, Wv, bv);

    dim3 ga(NSP / TI, BATCH);        // (64, 4) = 256 blocks, 2 CTAs/SM
    attn_kernel<<<ga, 128, SMEM_ATTN>>>(x, gamma, out);
}